// round 14
// baseline (speedup 1.0000x reference)
#include <cuda_runtime.h>
#include <math.h>

// Problem constants
#define O_DIM 32
#define I_DIM 32
#define K_DIM 13
#define N_DIM 4096
#define IK    (I_DIM * K_DIM)    // 416
#define WSIZE (O_DIM * IK)       // 13312 floats = 53 KB

#define THREADS 1024
#define BLOCKS  304              // 152 SMs * 2 resident blocks (all co-resident)
#define NGROUPS (N_DIM / 2)      // 2048 groups of 2 n's
#define ADDS_PER_LAUNCH (NGROUPS + BLOCKS)   // deterministic atomic count/launch

// Transposed x: xT[n][i] = x[i][n]  (4096 x 32 floats = 512 KB, L2-resident)
__device__ float xT[N_DIM * I_DIM];
// Grid-barrier epoch counter + work-steal counter (monotonic across replays)
__device__ unsigned int g_bar;
__device__ unsigned int wctr;

__global__ void __launch_bounds__(THREADS, 2) plaq_kernel(
    const float* __restrict__ x,       // (I, N)
    const float* __restrict__ W,       // (O, I, K)
    const float* __restrict__ b,       // (O,)
    const float* __restrict__ mask,    // (N, O, I, K)
    const int*   __restrict__ shifts,  // (N, K)
    float*       __restrict__ out)     // (O, N)
{
    __shared__ float Wsh[WSIZE];
    __shared__ float gsh[2][IK];       // [which-n][e], single-buffered (R9 style)
    __shared__ unsigned ids[2];        // ping-pong current/next stolen group id

    const int tid  = threadIdx.x;
    const int warp = tid >> 5;   // warp == o in the dot phase
    const int lane = tid & 31;
    const int bid  = blockIdx.x;

    // ---- Phase 1: in-kernel transpose (blocks 0..127, one 32x32 tile each).
    {
        float (*tile)[33] = (float(*)[33])Wsh;
        if (bid < N_DIM / 32) {
            const int n0t = bid * 32;
            tile[warp][lane] = x[warp * N_DIM + n0t + lane];
            __syncthreads();
            xT[(n0t + warp) * I_DIM + lane] = tile[lane][warp];
            __threadfence();               // publish xT before arriving
        }
        __syncthreads();                   // tile reads done before Wsh overwrite
    }

    // ---- Phase 2: load W into shared (overlaps other blocks' transpose work)
    #pragma unroll
    for (int e = tid; e < WSIZE; e += THREADS)
        Wsh[e] = W[e];
    __syncthreads();

    // ---- Phase 3: grid barrier + work-steal base (replay-safe epoch arithmetic)
    if (tid == 0) {
        const unsigned old    = atomicAdd(&g_bar, 1u);
        const unsigned target = (old / BLOCKS + 1u) * BLOCKS;
        while (atomicAdd(&g_bar, 0u) < target)
            __nanosleep(64);
        // launch index L = target/BLOCKS - 1; each launch does exactly
        // ADDS_PER_LAUNCH fetch-adds on wctr, so ids are launch-relative.
        const unsigned base = (target / BLOCKS - 1u) * ADDS_PER_LAUNCH;
        ids[0] = atomicAdd(&wctr, 1u) - base;   // prologue steal
        ids[1] = base;                          // stash base in ids[1] slot-free? no:
        // (base kept in tid0's register via the trick below)
    }
    __syncthreads();

    // tid0 keeps base in a register; other threads never need it.
    unsigned base_reg = 0;
    if (tid == 0) {
        // reconstruct base from ids[1] stash, then clear for ping-pong use
        base_reg = ids[1];
    }
    __syncthreads();

    // Gather mapping: warps 0..25 own (which, k); one xT row per warp per group
    const bool gw    = (warp < 2 * K_DIM);
    const int  which = (warp >= K_DIM) ? 1 : 0;
    const int  gk    = warp - which * K_DIM;

    const float bias = b[warp];
    const float e_const = 2.718281828459045f;
    const float scale = (2.0f + 2.0f * e_const) / (e_const - 1.0f);
    const float* __restrict__ wrow = Wsh + warp * IK;

    // ---- Phase 4: work-stealing loop, two n's per group, two barriers each
    int p = 0;
    for (;;) {
        const unsigned grp = ids[p];
        if (grp >= NGROUPS) break;
        const int n0 = 2 * (int)grp;

        // Gather both n's (in-phase, R9-proven) + steal next id (hidden here)
        if (gw) {
            const int s = shifts[(n0 + which) * K_DIM + gk];
            gsh[which][lane * K_DIM + gk] = xT[s * I_DIM + lane];
        }
        if (tid == 0)
            ids[p ^ 1] = atomicAdd(&wctr, 1u) - base_reg;
        __syncthreads();   // publishes gather + next id

        // Dot: 26 coalesced scalar mask LDGs per warp (13 per n)
        const float* __restrict__ m0 = mask + ((size_t)n0 * O_DIM + warp) * IK;
        const float* __restrict__ m1 = m0 + O_DIM * IK;

        float s0 = 0.0f, s1 = 0.0f;
        #pragma unroll
        for (int j = 0; j < K_DIM; ++j) {
            const int e = j * 32 + lane;     // 13*32 == 416 exactly
            const float w = wrow[e];
            s0 += m0[e] * w * gsh[0][e];
            s1 += m1[e] * w * gsh[1][e];
        }

        // Warp reductions
        #pragma unroll
        for (int off = 16; off > 0; off >>= 1) {
            s0 += __shfl_xor_sync(0xffffffffu, s0, off);
            s1 += __shfl_xor_sync(0xffffffffu, s1, off);
        }

        if (lane == 0) {
            const float y0 = s0 + bias;
            const float y1 = s1 + bias;
            out[warp * N_DIM + n0]     = (1.0f / (1.0f + __expf(-y0)) - 0.5f) * scale;
            out[warp * N_DIM + n0 + 1] = (1.0f / (1.0f + __expf(-y1)) - 0.5f) * scale;
        }

        __syncthreads();   // protects gsh + ids[p] before next iteration
        p ^= 1;
    }
}

// Tiny helper so tid0 can pass base through shared: done inline above via ids[1].
// NOTE: the prologue stores base into ids[1]; the first loop iteration reads
// ids[0] (a real group id) and tid0 overwrites ids[1] with the next steal, so
// the stash slot is consumed before the ping-pong ever reads it as a group.

extern "C" void kernel_launch(void* const* d_in, const int* in_sizes, int n_in,
                              void* d_out, int out_size) {
    const float* x      = (const float*)d_in[0];
    const float* Wconv  = (const float*)d_in[1];
    const float* bconv  = (const float*)d_in[2];
    const float* mask   = (const float*)d_in[3];
    const int*   shifts = (const int*)d_in[4];
    float* out          = (float*)d_out;

    plaq_kernel<<<BLOCKS, THREADS>>>(x, Wconv, bconv, mask, shifts, out);
}

// round 15
// speedup vs baseline: 1.1180x; 1.1180x over previous
#include <cuda_runtime.h>
#include <math.h>

// Problem constants
#define O_DIM 32
#define I_DIM 32
#define K_DIM 13
#define N_DIM 4096
#define IK    (I_DIM * K_DIM)    // 416
#define WSIZE (O_DIM * IK)       // 13312 floats = 53 KB

#define THREADS 1024
#define BLOCKS  304              // 152 SMs * 2 resident blocks (all co-resident)
#define MAX_NIT 14               // max n's per block: ceil(4096/304)
#define FULL_BLOCKS 144          // blocks 0..143 have 14 n's, rest 13

// Dynamic smem: Wsh (13312 floats) + gall (14*416 floats) = 76544 bytes
#define SMEM_BYTES ((WSIZE + MAX_NIT * IK) * 4)

// Transposed x: xT[n][i] = x[i][n]  (4096 x 32 floats = 512 KB, L2-resident)
__device__ float xT[N_DIM * I_DIM];
// Grid-barrier epoch counter (monotonic across graph replays)
__device__ unsigned int g_bar;

extern __shared__ float smem[];

__global__ void __launch_bounds__(THREADS, 2) plaq_kernel(
    const float* __restrict__ x,       // (I, N)
    const float* __restrict__ W,       // (O, I, K)
    const float* __restrict__ b,       // (O,)
    const float* __restrict__ mask,    // (N, O, I, K)
    const int*   __restrict__ shifts,  // (N, K)
    float*       __restrict__ out)     // (O, N)
{
    float* Wsh  = smem;                // WSIZE floats
    float* gall = smem + WSIZE;        // MAX_NIT * IK floats

    const int tid  = threadIdx.x;
    const int warp = tid >> 5;   // warp == o in the dot phase
    const int lane = tid & 31;
    const int bid  = blockIdx.x;

    // ---- Phase 1: in-kernel transpose (blocks 0..127, one 32x32 tile each).
    // Tile buffer aliases the head of Wsh (Wsh is written only after this phase).
    {
        float (*tile)[33] = (float(*)[33])Wsh;
        if (bid < N_DIM / 32) {
            const int n0t = bid * 32;
            tile[warp][lane] = x[warp * N_DIM + n0t + lane];
            __syncthreads();
            xT[(n0t + warp) * I_DIM + lane] = tile[lane][warp];
            __threadfence();               // publish xT before arriving
        }
        __syncthreads();                   // tile reads done before Wsh overwrite
    }

    // ---- Phase 2: load W into shared (overlaps other blocks' transpose work)
    #pragma unroll
    for (int e = tid; e < WSIZE; e += THREADS)
        Wsh[e] = W[e];

    // ---- Phase 3: software grid barrier (replay-safe epoch arithmetic)
    __syncthreads();
    if (tid == 0) {
        const unsigned old    = atomicAdd(&g_bar, 1u);
        const unsigned target = (old / BLOCKS + 1u) * BLOCKS;
        while (atomicAdd(&g_bar, 0u) < target)
            __nanosleep(64);
    }
    __syncthreads();

    // ---- Phase 4: gather ALL of this block's g vectors up front.
    // Row r = it*13 + k; one broadcast shift + one coalesced xT row + one STS.
    // STS address lane*13+k is conflict-free (13 coprime with 32).
    const int nit = (bid < FULL_BLOCKS) ? MAX_NIT : (MAX_NIT - 1);
    for (int r = warp; r < nit * K_DIM; r += 32) {
        const int it = r / K_DIM;
        const int k  = r - it * K_DIM;
        const int n  = bid + it * BLOCKS;
        const int s  = shifts[n * K_DIM + k];
        gall[it * IK + lane * K_DIM + k] = xT[s * I_DIM + lane];
    }
    __syncthreads();   // the LAST barrier — main loop below is barrier-free

    const float bias = b[warp];
    const float e_const = 2.718281828459045f;
    const float scale = (2.0f + 2.0f * e_const) / (e_const - 1.0f);
    const float* __restrict__ wrow = Wsh + warp * IK;

    // ---- Phase 5: barrier-free main loop — each warp free-runs over its n's
    for (int it = 0; it < nit; ++it) {
        const int n = bid + it * BLOCKS;
        const float* __restrict__ mrow = mask + ((size_t)n * O_DIM + warp) * IK;
        const float* __restrict__ g    = gall + it * IK;

        float sum = 0.0f;
        #pragma unroll
        for (int j = 0; j < K_DIM; ++j) {
            const int e = j * 32 + lane;     // 13*32 == 416 exactly
            sum += mrow[e] * wrow[e] * g[e];
        }

        #pragma unroll
        for (int off = 16; off > 0; off >>= 1)
            sum += __shfl_xor_sync(0xffffffffu, sum, off);

        if (lane == 0) {
            const float y = sum + bias;
            out[warp * N_DIM + n] = (1.0f / (1.0f + __expf(-y)) - 0.5f) * scale;
        }
    }
}

extern "C" void kernel_launch(void* const* d_in, const int* in_sizes, int n_in,
                              void* d_out, int out_size) {
    const float* x      = (const float*)d_in[0];
    const float* Wconv  = (const float*)d_in[1];
    const float* bconv  = (const float*)d_in[2];
    const float* mask   = (const float*)d_in[3];
    const int*   shifts = (const int*)d_in[4];
    float* out          = (float*)d_out;

    cudaFuncSetAttribute(plaq_kernel,
                         cudaFuncAttributeMaxDynamicSharedMemorySize, SMEM_BYTES);
    plaq_kernel<<<BLOCKS, THREADS, SMEM_BYTES>>>(x, Wconv, bconv, mask, shifts, out);
}

// round 16
// speedup vs baseline: 1.2117x; 1.0839x over previous
#include <cuda_runtime.h>
#include <math.h>

// Problem constants
#define O_DIM 32
#define I_DIM 32
#define K_DIM 13
#define N_DIM 4096
#define IK    (I_DIM * K_DIM)    // 416
#define WSIZE (O_DIM * IK)       // 13312 floats = 53 KB

#define THREADS 1024
#define BLOCKS  304              // 152 SMs * 2 resident blocks (all co-resident)

// Transposed x: xT[n][i] = x[i][n]  (4096 x 32 floats = 512 KB, L2-resident)
__device__ float xT[N_DIM * I_DIM];
// Grid-barrier epoch counter (monotonic across graph replays)
__device__ unsigned int g_bar;

__global__ void __launch_bounds__(THREADS, 2) plaq_kernel(
    const float* __restrict__ x,       // (I, N)
    const float* __restrict__ W,       // (O, I, K)
    const float* __restrict__ b,       // (O,)
    const float* __restrict__ mask,    // (N, O, I, K)
    const int*   __restrict__ shifts,  // (N, K)
    float*       __restrict__ out)     // (O, N)
{
    __shared__ float Wsh[WSIZE];
    __shared__ float gsh[2][IK];

    const int tid  = threadIdx.x;
    const int warp = tid >> 5;   // warp == o in the dot phase
    const int lane = tid & 31;
    const int bid  = blockIdx.x;

    // ---- Phase 1: in-kernel transpose (blocks 0..127, one 32x32 tile each).
    // Tile buffer aliases the head of Wsh (Wsh is written only after this phase).
    {
        float (*tile)[33] = (float(*)[33])Wsh;
        if (bid < N_DIM / 32) {
            const int n0t = bid * 32;
            tile[warp][lane] = x[warp * N_DIM + n0t + lane];
            __syncthreads();
            xT[(n0t + warp) * I_DIM + lane] = tile[lane][warp];
            __threadfence();               // publish xT before arriving
        }
        __syncthreads();                   // tile reads done before Wsh overwrite
    }

    // ---- Phase 2: load W into shared (overlaps other blocks' transpose work)
    #pragma unroll
    for (int e = tid; e < WSIZE; e += THREADS)
        Wsh[e] = W[e];
    __syncthreads();

    // ---- Phase 3: software grid barrier (replay-safe epoch arithmetic)
    if (tid == 0) {
        const unsigned old    = atomicAdd(&g_bar, 1u);
        const unsigned target = (old / BLOCKS + 1u) * BLOCKS;
        while (atomicAdd(&g_bar, 0u) < target)
            __nanosleep(64);
    }
    __syncthreads();

    const float bias = b[warp];
    const float e_const = 2.718281828459045f;
    const float scale = (2.0f + 2.0f * e_const) / (e_const - 1.0f);
    const float* __restrict__ wrow = Wsh + warp * IK;

    // ---- Phase 4: main loop, two n's per iteration (R9 structure; mask loads
    // use __ldcs so the zero-reuse 218MB stream doesn't evict xT/shifts from L2)
    for (int n0 = 2 * bid; n0 < N_DIM; n0 += 2 * BLOCKS) {
        // Gather both n's: warp k (k<13) -> n0, warp 13+k -> n0+1.
        // One broadcast shift + one 128B xT row per warp; STS lane*13+k is
        // conflict-free (13 coprime with 32).
        if (warp < 2 * K_DIM) {
            const int which = (warp >= K_DIM) ? 1 : 0;
            const int k     = warp - which * K_DIM;
            const int s     = shifts[(n0 + which) * K_DIM + k];
            gsh[which][lane * K_DIM + k] = xT[s * I_DIM + lane];
        }
        __syncthreads();

        // Dot: 26 coalesced scalar mask LDG.CS per warp (13 per n)
        const float* __restrict__ m0 = mask + ((size_t)n0 * O_DIM + warp) * IK;
        const float* __restrict__ m1 = m0 + O_DIM * IK;

        float s0 = 0.0f, s1 = 0.0f;
        #pragma unroll
        for (int j = 0; j < K_DIM; ++j) {
            const int e = j * 32 + lane;     // 13*32 == 416 exactly
            const float w = wrow[e];
            s0 += __ldcs(m0 + e) * w * gsh[0][e];
            s1 += __ldcs(m1 + e) * w * gsh[1][e];
        }

        // Warp reductions
        #pragma unroll
        for (int off = 16; off > 0; off >>= 1) {
            s0 += __shfl_xor_sync(0xffffffffu, s0, off);
            s1 += __shfl_xor_sync(0xffffffffu, s1, off);
        }

        if (lane == 0) {
            const float y0 = s0 + bias;
            const float y1 = s1 + bias;
            out[warp * N_DIM + n0]     = (1.0f / (1.0f + __expf(-y0)) - 0.5f) * scale;
            out[warp * N_DIM + n0 + 1] = (1.0f / (1.0f + __expf(-y1)) - 0.5f) * scale;
        }
        __syncthreads();   // protect gsh before next iteration overwrites it
    }
}

extern "C" void kernel_launch(void* const* d_in, const int* in_sizes, int n_in,
                              void* d_out, int out_size) {
    const float* x      = (const float*)d_in[0];
    const float* Wconv  = (const float*)d_in[1];
    const float* bconv  = (const float*)d_in[2];
    const float* mask   = (const float*)d_in[3];
    const int*   shifts = (const int*)d_in[4];
    float* out          = (float*)d_out;

    plaq_kernel<<<BLOCKS, THREADS>>>(x, Wconv, bconv, mask, shifts, out);
}